// round 13
// baseline (speedup 1.0000x reference)
#include <cuda_runtime.h>
#include <cuda_fp16.h>
#include <cstdint>

// ---------------------------------------------------------------------------
// Problem dims
// ---------------------------------------------------------------------------
#define M_TOT 8192
#define N_TOT 4096
#define K_TOT 4096

// GEMM tiling: 128x128 CTA tile, 4 warps (2x2) of 64x64, 2 CTAs/SM,
// PERSISTENT grid of 296 CTAs (148 SMs x occ 2).
#define TM 128
#define TN 128
#define TK 64
#define STAGES 3
#define NKT (K_TOT / TK)                    // 64 k-iterations per tile
#define NTILES_N (N_TOT / TN)               // 32
#define NTILES (M_TOT / TM * NTILES_N)      // 2048
#define GRID_P 296                          // persistent CTAs (148 SMs x 2)
#define A_STAGE_BYTES (TM * TK * 2)         // 16384
#define B_STAGE_BYTES (TN * TK * 2)         // 16384
#define STAGE_BYTES (A_STAGE_BYTES + B_STAGE_BYTES)   // 32768
#define SMEM_TOTAL (1024 + STAGES * STAGE_BYTES)      // 99328 (x2 CTAs = 194KB/SM)

// ---------------------------------------------------------------------------
// Scratch (allocation-guard-safe __device__ globals)
// ---------------------------------------------------------------------------
__device__ __half g_X[(size_t)M_TOT * K_TOT];   // 64 MB fp16 activations
__device__ __half g_W[(size_t)N_TOT * K_TOT];   // 32 MB fp16 decompressed weights

// ---------------------------------------------------------------------------
// PTX helpers (base-ISA only: cp.async sm_80, mbarrier, ldmatrix/mma)
// ---------------------------------------------------------------------------
__device__ __forceinline__ uint32_t smem_u32(const void* p) {
    uint32_t a;
    asm("{ .reg .u64 t; cvta.to.shared.u64 t, %1; cvt.u32.u64 %0, t; }" : "=r"(a) : "l"(p));
    return a;
}

__device__ __forceinline__ void cp_async16(uint32_t dst, const void* src) {
    asm volatile("cp.async.cg.shared.global [%0], [%1], 16;" :: "r"(dst), "l"(src) : "memory");
}

#define MBARRIER_INIT(mbar, count) \
    asm volatile("mbarrier.init.shared.b64 [%0], %1;" :: "r"((uint32_t)(mbar)), "r"((uint32_t)(count)) : "memory")

#define MBARRIER_ARRIVE(mbar) \
    asm volatile("mbarrier.arrive.shared.b64 _, [%0];" :: "r"((uint32_t)(mbar)) : "memory")

// Arrive on mbar when ALL of this thread's prior cp.asyncs have completed.
#define CP_ASYNC_MBAR_ARRIVE(mbar) \
    asm volatile("cp.async.mbarrier.arrive.noinc.shared.b64 [%0];" :: "r"((uint32_t)(mbar)) : "memory")

#define MBARRIER_WAIT_PARITY(mbar, parity) do {                                     \
    uint32_t _m = (uint32_t)(mbar); uint32_t _p = (uint32_t)(parity); uint32_t _d;  \
    asm volatile("{\n\t.reg .pred p;\n\t"                                           \
        "mbarrier.try_wait.parity.acquire.cta.shared::cta.b64 p, [%1], %2;\n\t"     \
        "selp.b32 %0, 1, 0, p;\n\t}"                                                \
        : "=r"(_d) : "r"(_m), "r"(_p) : "memory");                                  \
    if (!_d) {                                                                      \
        asm volatile("{\n\t.reg .pred P1;\n\t"                                      \
            "WL_%=:\n\t"                                                            \
            "mbarrier.try_wait.parity.acquire.cta.shared::cta.b64 P1, [%0], %1, 0x989680;\n\t" \
            "@P1 bra.uni WD_%=;\n\t"                                                \
            "bra.uni WL_%=;\n\t"                                                    \
            "WD_%=:\n\t}"                                                           \
            :: "r"(_m), "r"(_p) : "memory");                                        \
    }                                                                               \
} while (0)

__device__ __forceinline__ void ldsm_x4(uint32_t& r0, uint32_t& r1, uint32_t& r2, uint32_t& r3,
                                        uint32_t addr) {
    asm volatile("ldmatrix.sync.aligned.m8n8.x4.shared.b16 {%0,%1,%2,%3}, [%4];"
                 : "=r"(r0), "=r"(r1), "=r"(r2), "=r"(r3) : "r"(addr));
}

__device__ __forceinline__ void mma16816(float* d, const uint32_t* a, const uint32_t* b) {
    asm volatile(
        "mma.sync.aligned.m16n8k16.row.col.f32.f16.f16.f32 "
        "{%0,%1,%2,%3}, {%4,%5,%6,%7}, {%8,%9}, {%0,%1,%2,%3};"
        : "+f"(d[0]), "+f"(d[1]), "+f"(d[2]), "+f"(d[3])
        : "r"(a[0]), "r"(a[1]), "r"(a[2]), "r"(a[3]), "r"(b[0]), "r"(b[1]));
}

// ---------------------------------------------------------------------------
// Kernel 1 (fused prologue): blocks [0, 16384) convert x fp32->fp16;
// blocks [16384, 32768) decompress W[o][i] = fp16(cb[o][idx[o][i]]).
// ---------------------------------------------------------------------------
__global__ void prep_kernel(const float* __restrict__ x,
                            const int* __restrict__ idx,
                            const float* __restrict__ cb,
                            __half* __restrict__ oX,
                            __half* __restrict__ oW) {
    int b = blockIdx.x;
    if (b < 16384) {
        size_t t = (size_t)b * blockDim.x + threadIdx.x;
        size_t base = t * 8;
        float4 a = *reinterpret_cast<const float4*>(x + base);
        float4 c = *reinterpret_cast<const float4*>(x + base + 4);
        __half2 h0 = __floats2half2_rn(a.x, a.y);
        __half2 h1 = __floats2half2_rn(a.z, a.w);
        __half2 h2 = __floats2half2_rn(c.x, c.y);
        __half2 h3 = __floats2half2_rn(c.z, c.w);
        uint4 u;
        u.x = *reinterpret_cast<uint32_t*>(&h0);
        u.y = *reinterpret_cast<uint32_t*>(&h1);
        u.z = *reinterpret_cast<uint32_t*>(&h2);
        u.w = *reinterpret_cast<uint32_t*>(&h3);
        *reinterpret_cast<uint4*>(oX + base) = u;
    } else {
        size_t t = (size_t)(b - 16384) * blockDim.x + threadIdx.x;
        size_t base = t * 4;
        int4 i4 = *reinterpret_cast<const int4*>(idx + base);
        const float* crow = cb + ((base >> 12) << 8);  // row = base/4096, *256 entries
        __half2 h0 = __floats2half2_rn(crow[i4.x], crow[i4.y]);
        __half2 h1 = __floats2half2_rn(crow[i4.z], crow[i4.w]);
        uint2 u;
        u.x = *reinterpret_cast<uint32_t*>(&h0);
        u.y = *reinterpret_cast<uint32_t*>(&h1);
        *reinterpret_cast<uint2*>(oW + base) = u;
    }
}

// ---------------------------------------------------------------------------
// Kernel 2: PERSISTENT GEMM. 296 CTAs; each walks tiles bid, bid+296, ...
// The 3-stage mbarrier ring NEVER drains at tile boundaries: fill cursor
// (tf, ktf, gf) runs ahead of the consume cursor (gc) across tiles, so the
// next tile's loads fly during the current tile's last MMAs and epilogue.
// ---------------------------------------------------------------------------
__global__ void __launch_bounds__(128, 2) gemm_kernel(
    const __half* __restrict__ A,      // [M_TOT, K_TOT] row-major
    const __half* __restrict__ B,      // [N_TOT, K_TOT] row-major (= col-major B)
    const float* __restrict__ bias,
    float* __restrict__ out)
{
    extern __shared__ char smem[];
    const uint32_t sb = smem_u32(smem);
    const int tid = threadIdx.x, wid = tid >> 5, lane = tid & 31;
    const int warp_m = wid & 1;        // 2 warps along M
    const int warp_n = wid >> 1;       // 2 warps along N
    const int bid = blockIdx.x;

    // mbarriers: full[0..2] at sb+0..23, empty[0..2] at sb+24..47; data at sb+1024
    const uint32_t BFULL  = sb;
    const uint32_t BEMPTY = sb + 8 * STAGES;
    const uint32_t DATA0  = sb + 1024;

    // cp.async (row, chunk): 8 chunks of 16B per 128B row, 16 rows/pass (128 thr)
    const int ld_row = tid >> 3;       // 0..15
    const int ld_ch  = tid & 7;
    const int ld_sw  = (ld_ch ^ (ld_row & 7)) << 4;

    if (tid == 0) {
        #pragma unroll
        for (int s = 0; s < STAGES; s++) {
            MBARRIER_INIT(BFULL + 8 * s, 128);   // one async-arrive per thread
            MBARRIER_INIT(BEMPTY + 8 * s, 4);    // one arrive per warp
        }
    }
    __syncthreads();

    // --- stage filler for (tile t, k-tile kt) into slot s ---
    auto fill_stage = [&](int t, int kt, int s) {
        const __half* gA = A + (size_t)((t >> 5) * TM) * K_TOT + kt * TK;
        const __half* gB = B + (size_t)((t & 31) * TN) * K_TOT + kt * TK;
        uint32_t base = DATA0 + s * STAGE_BYTES;
        #pragma unroll
        for (int i = 0; i < TM / 16; i++) {           // 8 iters: 128 rows
            int row = ld_row + i * 16;
            cp_async16(base + row * 128 + ld_sw, gA + (size_t)row * K_TOT + ld_ch * 8);
        }
        uint32_t baseB = base + A_STAGE_BYTES;
        #pragma unroll
        for (int i = 0; i < TN / 16; i++) {           // 8 iters: 128 rows
            int row = ld_row + i * 16;
            cp_async16(baseB + row * 128 + ld_sw, gB + (size_t)row * K_TOT + ld_ch * 8);
        }
        CP_ASYNC_MBAR_ARRIVE(BFULL + 8 * s);
    };

    // --- ldmatrix per-lane geometry (64x64 warp tile) ---
    const int asub  = lane >> 3;
    const int a_row = warp_m * 64 + ((asub & 1) << 3) + (lane & 7);
    const int a_cof = asub >> 1;
    const int a_xor = a_row & 7;
    uint32_t aRowB[4];
    #pragma unroll
    for (int mf = 0; mf < 4; mf++) aRowB[mf] = (a_row + mf * 16) * 128;

    const int bsub  = lane >> 3;
    const int b_row = warp_n * 64 + ((bsub >> 1) << 3) + (lane & 7);
    const int b_cof = bsub & 1;
    const int b_xor = b_row & 7;
    uint32_t bRowB[4];
    #pragma unroll
    for (int p = 0; p < 4; p++) bRowB[p] = (b_row + p * 16) * 128;

    float acc[4][8][4];
    #pragma unroll
    for (int mf = 0; mf < 4; mf++)
        #pragma unroll
        for (int nf = 0; nf < 8; nf++)
            #pragma unroll
            for (int r = 0; r < 4; r++) acc[mf][nf][r] = 0.f;

    // --- fill cursor (runs STAGES-1 items ahead of consume cursor) ---
    int tf = bid, ktf = 0;    // next (tile, kt) to fill
    int gf = 0;               // global fill counter (slot = gf % STAGES)
    auto advance_fill = [&]() {
        if (++ktf == NKT) { ktf = 0; tf += GRID_P; }
    };

    // --- prologue: fill first STAGES-1 items ---
    #pragma unroll
    for (int s = 0; s < STAGES - 1; s++) {
        if (tf < NTILES) { fill_stage(tf, ktf, gf % STAGES); advance_fill(); gf++; }
    }

    // --- persistent mainloop over tiles ---
    int gc = 0;               // global consume counter
    for (int t = bid; t < NTILES; t += GRID_P) {
        for (int kt = 0; kt < NKT; kt++, gc++) {
            int s = gc % STAGES;
            int n = gc / STAGES;

            MBARRIER_WAIT_PARITY(BFULL + 8 * s, n & 1);
            uint32_t aBase = DATA0 + s * STAGE_BYTES;
            uint32_t bBase = aBase + A_STAGE_BYTES;

            #pragma unroll
            for (int ks = 0; ks < TK / 16; ks++) {        // 4 k-steps of 16
                uint32_t af[4][4];
                #pragma unroll
                for (int mf = 0; mf < 4; mf++) {
                    uint32_t addr = aBase + aRowB[mf] + ((((ks << 1) + a_cof) ^ a_xor) << 4);
                    ldsm_x4(af[mf][0], af[mf][1], af[mf][2], af[mf][3], addr);
                }
                uint32_t bf[8][2];
                #pragma unroll
                for (int p = 0; p < 4; p++) {
                    uint32_t r0, r1, r2, r3;
                    uint32_t addr = bBase + bRowB[p] + ((((ks << 1) + b_cof) ^ b_xor) << 4);
                    ldsm_x4(r0, r1, r2, r3, addr);
                    bf[2 * p][0] = r0;     bf[2 * p][1] = r1;
                    bf[2 * p + 1][0] = r2; bf[2 * p + 1][1] = r3;
                }
                // Last ldsm of this stage is done — release the slot early.
                if (ks == TK / 16 - 1 && lane == 0) MBARRIER_ARRIVE(BEMPTY + 8 * s);
                #pragma unroll
                for (int mf = 0; mf < 4; mf++)
                    #pragma unroll
                    for (int nf = 0; nf < 8; nf++)
                        mma16816(acc[mf][nf], af[mf], bf[nf]);
            }

            // produce next item (crosses tile boundaries seamlessly)
            if (tf < NTILES) {
                int sL = gf % STAGES;
                int nL = gf / STAGES;
                if (nL > 0) MBARRIER_WAIT_PARITY(BEMPTY + 8 * sL, (nL - 1) & 1);
                fill_stage(tf, ktf, sL);
                advance_fill(); gf++;
            }
        }

        // --- per-tile epilogue (overlaps with next tile's in-flight fills) ---
        const int row0 = (t >> 5) * TM + warp_m * 64 + (lane >> 2);
        const int col0 = (t & 31) * TN + warp_n * 64 + ((lane & 3) << 1);
        float bv[8][2];
        #pragma unroll
        for (int nf = 0; nf < 8; nf++) {
            bv[nf][0] = __ldg(&bias[col0 + nf * 8]);
            bv[nf][1] = __ldg(&bias[col0 + nf * 8 + 1]);
        }
        #pragma unroll
        for (int mf = 0; mf < 4; mf++) {
            #pragma unroll
            for (int h = 0; h < 2; h++) {
                size_t r = (size_t)(row0 + mf * 16 + h * 8);
                float* orow = out + r * N_TOT;
                #pragma unroll
                for (int nf = 0; nf < 8; nf++) {
                    float2 v;
                    v.x = acc[mf][nf][2 * h + 0] + bv[nf][0];
                    v.y = acc[mf][nf][2 * h + 1] + bv[nf][1];
                    *reinterpret_cast<float2*>(orow + col0 + nf * 8) = v;
                }
            }
        }
        // reset accumulators for the next tile
        #pragma unroll
        for (int mf = 0; mf < 4; mf++)
            #pragma unroll
            for (int nf = 0; nf < 8; nf++)
                #pragma unroll
                for (int r = 0; r < 4; r++) acc[mf][nf][r] = 0.f;
    }
}

// ---------------------------------------------------------------------------
// Host launch — inputs identified BY ELEMENT COUNT (robust to ordering):
//   x: 33554432 (f32), codebook: 1048576 (f32), bias: 4096 (f32),
//   indices: 16777216 (int32 — harness has no int64)
// ---------------------------------------------------------------------------
extern "C" void kernel_launch(void* const* d_in, const int* in_sizes, int n_in,
                              void* d_out, int out_size) {
    const float* x        = nullptr;
    const float* codebook = nullptr;
    const float* bias     = nullptr;
    const int*   indices  = nullptr;

    for (int i = 0; i < n_in; i++) {
        switch (in_sizes[i]) {
            case 33554432: x        = (const float*)d_in[i]; break;
            case 1048576:  codebook = (const float*)d_in[i]; break;
            case 4096:     bias     = (const float*)d_in[i]; break;
            case 16777216: indices  = (const int*)d_in[i];   break;
            default: break;
        }
    }
    float* out = (float*)d_out;   // [8192, 4096] fp32

    void* pX = nullptr; void* pW = nullptr;
    cudaGetSymbolAddress(&pX, g_X);
    cudaGetSymbolAddress(&pW, g_W);

    cudaFuncSetAttribute(gemm_kernel, cudaFuncAttributeMaxDynamicSharedMemorySize, SMEM_TOTAL);

    // 1) fused prologue: 16384 cvt blocks + 16384 decomp blocks, one launch
    prep_kernel<<<32768, 256>>>(x, indices, codebook, (__half*)pX, (__half*)pW);
    // 2) persistent GEMM: 296 CTAs (148 SMs x 2), tiles walked bid, bid+296, ...
    gemm_kernel<<<GRID_P, 128, SMEM_TOTAL>>>(
        (const __half*)pX, (const __half*)pW, bias, out);
}

// round 14
// speedup vs baseline: 1.0346x; 1.0346x over previous
#include <cuda_runtime.h>
#include <cuda_fp16.h>
#include <cstdint>

// ---------------------------------------------------------------------------
// Problem dims
// ---------------------------------------------------------------------------
#define M_TOT 8192
#define N_TOT 4096
#define K_TOT 4096

// GEMM tiling: 128x128 CTA tile, 4 warps (2x2) of 64x64, 2 CTAs/SM (R12 config)
#define TM 128
#define TN 128
#define TK 64
#define STAGES 3
#define NKT (K_TOT / TK)                    // 64 k-iterations
#define A_STAGE_BYTES (TM * TK * 2)         // 16384
#define B_STAGE_BYTES (TN * TK * 2)         // 16384
#define STAGE_BYTES (A_STAGE_BYTES + B_STAGE_BYTES)   // 32768
#define SMEM_TOTAL (1024 + STAGES * STAGE_BYTES)      // 99328 (x2 CTAs = 194KB/SM)

// ---------------------------------------------------------------------------
// Scratch (allocation-guard-safe __device__ globals)
// ---------------------------------------------------------------------------
__device__ __half g_X[(size_t)M_TOT * K_TOT];   // 64 MB fp16 activations
__device__ __half g_W[(size_t)N_TOT * K_TOT];   // 32 MB fp16 decompressed weights

// ---------------------------------------------------------------------------
// PTX helpers (base-ISA only: cp.async sm_80, mbarrier, ldmatrix/mma)
// ---------------------------------------------------------------------------
__device__ __forceinline__ uint32_t smem_u32(const void* p) {
    uint32_t a;
    asm("{ .reg .u64 t; cvta.to.shared.u64 t, %1; cvt.u32.u64 %0, t; }" : "=r"(a) : "l"(p));
    return a;
}

__device__ __forceinline__ void cp_async16(uint32_t dst, const void* src) {
    asm volatile("cp.async.cg.shared.global [%0], [%1], 16;" :: "r"(dst), "l"(src) : "memory");
}

// streaming (evict-first) 8-byte store — keeps the 128MB output from
// displacing the L2-resident A/W working set
__device__ __forceinline__ void stg_cs_v2(float* p, float x, float y) {
    asm volatile("st.global.cs.v2.f32 [%0], {%1, %2};" :: "l"(p), "f"(x), "f"(y) : "memory");
}

#define MBARRIER_INIT(mbar, count) \
    asm volatile("mbarrier.init.shared.b64 [%0], %1;" :: "r"((uint32_t)(mbar)), "r"((uint32_t)(count)) : "memory")

#define MBARRIER_ARRIVE(mbar) \
    asm volatile("mbarrier.arrive.shared.b64 _, [%0];" :: "r"((uint32_t)(mbar)) : "memory")

// Arrive on mbar when ALL of this thread's prior cp.asyncs have completed.
#define CP_ASYNC_MBAR_ARRIVE(mbar) \
    asm volatile("cp.async.mbarrier.arrive.noinc.shared.b64 [%0];" :: "r"((uint32_t)(mbar)) : "memory")

#define MBARRIER_WAIT_PARITY(mbar, parity) do {                                     \
    uint32_t _m = (uint32_t)(mbar); uint32_t _p = (uint32_t)(parity); uint32_t _d;  \
    asm volatile("{\n\t.reg .pred p;\n\t"                                           \
        "mbarrier.try_wait.parity.acquire.cta.shared::cta.b64 p, [%1], %2;\n\t"     \
        "selp.b32 %0, 1, 0, p;\n\t}"                                                \
        : "=r"(_d) : "r"(_m), "r"(_p) : "memory");                                  \
    if (!_d) {                                                                      \
        asm volatile("{\n\t.reg .pred P1;\n\t"                                      \
            "WL_%=:\n\t"                                                            \
            "mbarrier.try_wait.parity.acquire.cta.shared::cta.b64 P1, [%0], %1, 0x989680;\n\t" \
            "@P1 bra.uni WD_%=;\n\t"                                                \
            "bra.uni WL_%=;\n\t"                                                    \
            "WD_%=:\n\t}"                                                           \
            :: "r"(_m), "r"(_p) : "memory");                                        \
    }                                                                               \
} while (0)

__device__ __forceinline__ void ldsm_x4(uint32_t& r0, uint32_t& r1, uint32_t& r2, uint32_t& r3,
                                        uint32_t addr) {
    asm volatile("ldmatrix.sync.aligned.m8n8.x4.shared.b16 {%0,%1,%2,%3}, [%4];"
                 : "=r"(r0), "=r"(r1), "=r"(r2), "=r"(r3) : "r"(addr));
}

__device__ __forceinline__ void mma16816(float* d, const uint32_t* a, const uint32_t* b) {
    asm volatile(
        "mma.sync.aligned.m16n8k16.row.col.f32.f16.f16.f32 "
        "{%0,%1,%2,%3}, {%4,%5,%6,%7}, {%8,%9}, {%0,%1,%2,%3};"
        : "+f"(d[0]), "+f"(d[1]), "+f"(d[2]), "+f"(d[3])
        : "r"(a[0]), "r"(a[1]), "r"(a[2]), "r"(a[3]), "r"(b[0]), "r"(b[1]));
}

// ---------------------------------------------------------------------------
// Kernel 1 (fused prologue): blocks [0, 16384) convert x fp32->fp16;
// blocks [16384, 32768) decompress W[o][i] = fp16(cb[o][idx[o][i]]).
// ---------------------------------------------------------------------------
__global__ void prep_kernel(const float* __restrict__ x,
                            const int* __restrict__ idx,
                            const float* __restrict__ cb,
                            __half* __restrict__ oX,
                            __half* __restrict__ oW) {
    int b = blockIdx.x;
    if (b < 16384) {
        size_t t = (size_t)b * blockDim.x + threadIdx.x;
        size_t base = t * 8;
        float4 a = *reinterpret_cast<const float4*>(x + base);
        float4 c = *reinterpret_cast<const float4*>(x + base + 4);
        __half2 h0 = __floats2half2_rn(a.x, a.y);
        __half2 h1 = __floats2half2_rn(a.z, a.w);
        __half2 h2 = __floats2half2_rn(c.x, c.y);
        __half2 h3 = __floats2half2_rn(c.z, c.w);
        uint4 u;
        u.x = *reinterpret_cast<uint32_t*>(&h0);
        u.y = *reinterpret_cast<uint32_t*>(&h1);
        u.z = *reinterpret_cast<uint32_t*>(&h2);
        u.w = *reinterpret_cast<uint32_t*>(&h3);
        *reinterpret_cast<uint4*>(oX + base) = u;
    } else {
        size_t t = (size_t)(b - 16384) * blockDim.x + threadIdx.x;
        size_t base = t * 4;
        int4 i4 = *reinterpret_cast<const int4*>(idx + base);
        const float* crow = cb + ((base >> 12) << 8);  // row = base/4096, *256 entries
        __half2 h0 = __floats2half2_rn(crow[i4.x], crow[i4.y]);
        __half2 h1 = __floats2half2_rn(crow[i4.z], crow[i4.w]);
        uint2 u;
        u.x = *reinterpret_cast<uint32_t*>(&h0);
        u.y = *reinterpret_cast<uint32_t*>(&h1);
        *reinterpret_cast<uint2*>(oW + base) = u;
    }
}

// ---------------------------------------------------------------------------
// Kernel 2: GEMM — exact R12 config (best measured: 659.5us, tensor 81.3%):
// 128x128 CTA tile, 4 warps (2x2) of 64x64, K-tile 64, 3-stage cp.async
// pipeline with per-stage mbarriers, 2 CTAs/SM, early empty-arrive.
// R14 tweaks: bias preloaded before the mainloop; output via st.global.cs.
// ---------------------------------------------------------------------------
__global__ void __launch_bounds__(128, 2) gemm_kernel(
    const __half* __restrict__ A,      // [M_TOT, K_TOT] row-major
    const __half* __restrict__ B,      // [N_TOT, K_TOT] row-major (= col-major B)
    const float* __restrict__ bias,
    float* __restrict__ out)
{
    extern __shared__ char smem[];
    const uint32_t sb = smem_u32(smem);
    const int tid = threadIdx.x, wid = tid >> 5, lane = tid & 31;
    const int warp_m = wid & 1;        // 2 warps along M
    const int warp_n = wid >> 1;       // 2 warps along N
    const int tile_n = blockIdx.x, tile_m = blockIdx.y;

    // mbarriers: full[0..2] at sb+0..23, empty[0..2] at sb+24..47; data at sb+1024
    const uint32_t BFULL  = sb;
    const uint32_t BEMPTY = sb + 8 * STAGES;
    const uint32_t DATA0  = sb + 1024;

    const __half* gA = A + (size_t)(tile_m * TM) * K_TOT;
    const __half* gB = B + (size_t)(tile_n * TN) * K_TOT;

    // cp.async (row, chunk): 8 chunks of 16B per 128B row, 16 rows/pass (128 thr)
    const int ld_row = tid >> 3;       // 0..15
    const int ld_ch  = tid & 7;
    const int ld_sw  = (ld_ch ^ (ld_row & 7)) << 4;

    if (tid == 0) {
        #pragma unroll
        for (int s = 0; s < STAGES; s++) {
            MBARRIER_INIT(BFULL + 8 * s, 128);   // one async-arrive per thread
            MBARRIER_INIT(BEMPTY + 8 * s, 4);    // one arrive per warp
        }
    }
    __syncthreads();

    // --- stage filler: 16 cp.asyncs per thread, then async-arrive on full[s] ---
    auto fill_stage = [&](int kt, int s) {
        uint32_t base = DATA0 + s * STAGE_BYTES;
        const __half* srcA = gA + kt * TK;
        #pragma unroll
        for (int i = 0; i < TM / 16; i++) {           // 8 iters: 128 rows
            int row = ld_row + i * 16;
            cp_async16(base + row * 128 + ld_sw, srcA + (size_t)row * K_TOT + ld_ch * 8);
        }
        uint32_t baseB = base + A_STAGE_BYTES;
        const __half* srcB = gB + kt * TK;
        #pragma unroll
        for (int i = 0; i < TN / 16; i++) {           // 8 iters: 128 rows
            int row = ld_row + i * 16;
            cp_async16(baseB + row * 128 + ld_sw, srcB + (size_t)row * K_TOT + ld_ch * 8);
        }
        CP_ASYNC_MBAR_ARRIVE(BFULL + 8 * s);
    };

    // --- ldmatrix per-lane geometry (64x64 warp tile) ---
    const int asub  = lane >> 3;
    const int a_row = warp_m * 64 + ((asub & 1) << 3) + (lane & 7);
    const int a_cof = asub >> 1;
    const int a_xor = a_row & 7;
    uint32_t aRowB[4];
    #pragma unroll
    for (int mf = 0; mf < 4; mf++) aRowB[mf] = (a_row + mf * 16) * 128;

    const int bsub  = lane >> 3;
    const int b_row = warp_n * 64 + ((bsub >> 1) << 3) + (lane & 7);
    const int b_cof = bsub & 1;
    const int b_xor = b_row & 7;
    uint32_t bRowB[4];
    #pragma unroll
    for (int p = 0; p < 4; p++) bRowB[p] = (b_row + p * 16) * 128;

    float acc[4][8][4];
    #pragma unroll
    for (int mf = 0; mf < 4; mf++)
        #pragma unroll
        for (int nf = 0; nf < 8; nf++)
            #pragma unroll
            for (int r = 0; r < 4; r++) acc[mf][nf][r] = 0.f;

    // --- bias preload (CTA-fixed columns; hides ~L2 latency off the epilogue) ---
    const int col0 = tile_n * TN + warp_n * 64 + ((lane & 3) << 1);
    float bv[8][2];
    #pragma unroll
    for (int nf = 0; nf < 8; nf++) {
        bv[nf][0] = __ldg(&bias[col0 + nf * 8]);
        bv[nf][1] = __ldg(&bias[col0 + nf * 8 + 1]);
    }

    // --- prologue: fill first STAGES-1 stages (slots never used before) ---
    #pragma unroll
    for (int s = 0; s < STAGES - 1; s++) fill_stage(s, s);

    // --- mainloop: mbarrier producer/consumer, no __syncthreads ---
    for (int kt = 0; kt < NKT; kt++) {
        int s = kt % STAGES;
        int n = kt / STAGES;

        MBARRIER_WAIT_PARITY(BFULL + 8 * s, n & 1);
        uint32_t aBase = DATA0 + s * STAGE_BYTES;
        uint32_t bBase = aBase + A_STAGE_BYTES;

        #pragma unroll
        for (int ks = 0; ks < TK / 16; ks++) {        // 4 k-steps of 16
            uint32_t af[4][4];
            #pragma unroll
            for (int mf = 0; mf < 4; mf++) {
                uint32_t addr = aBase + aRowB[mf] + ((((ks << 1) + a_cof) ^ a_xor) << 4);
                ldsm_x4(af[mf][0], af[mf][1], af[mf][2], af[mf][3], addr);
            }
            uint32_t bf[8][2];
            #pragma unroll
            for (int p = 0; p < 4; p++) {
                uint32_t r0, r1, r2, r3;
                uint32_t addr = bBase + bRowB[p] + ((((ks << 1) + b_cof) ^ b_xor) << 4);
                ldsm_x4(r0, r1, r2, r3, addr);
                bf[2 * p][0] = r0;     bf[2 * p][1] = r1;
                bf[2 * p + 1][0] = r2; bf[2 * p + 1][1] = r3;
            }
            // Last ldsm of this stage is done — release the slot early
            // (registers hold all remaining data; MMAs don't read smem).
            if (ks == TK / 16 - 1 && lane == 0) MBARRIER_ARRIVE(BEMPTY + 8 * s);
            #pragma unroll
            for (int mf = 0; mf < 4; mf++)
                #pragma unroll
                for (int nf = 0; nf < 8; nf++)
                    mma16816(acc[mf][nf], af[mf], bf[nf]);
        }

        // produce: refill slot for kt+STAGES-1 (wait for consumption of its
        // previous use first; use 0 was the prologue, no wait needed)
        int ktL = kt + STAGES - 1;
        if (ktL < NKT) {
            int sL = ktL % STAGES;
            int nL = ktL / STAGES;
            if (nL > 0) MBARRIER_WAIT_PARITY(BEMPTY + 8 * sL, (nL - 1) & 1);
            fill_stage(ktL, sL);
        }
    }

    // --- epilogue: bias add + streaming fp32 stores (evict-first) ---
    const int row0 = tile_m * TM + warp_m * 64 + (lane >> 2);
    #pragma unroll
    for (int mf = 0; mf < 4; mf++) {
        #pragma unroll
        for (int h = 0; h < 2; h++) {
            size_t r = (size_t)(row0 + mf * 16 + h * 8);
            float* orow = out + r * N_TOT;
            #pragma unroll
            for (int nf = 0; nf < 8; nf++) {
                stg_cs_v2(orow + col0 + nf * 8,
                          acc[mf][nf][2 * h + 0] + bv[nf][0],
                          acc[mf][nf][2 * h + 1] + bv[nf][1]);
            }
        }
    }
}

// ---------------------------------------------------------------------------
// Host launch — inputs identified BY ELEMENT COUNT (robust to ordering):
//   x: 33554432 (f32), codebook: 1048576 (f32), bias: 4096 (f32),
//   indices: 16777216 (int32 — harness has no int64)
// ---------------------------------------------------------------------------
extern "C" void kernel_launch(void* const* d_in, const int* in_sizes, int n_in,
                              void* d_out, int out_size) {
    const float* x        = nullptr;
    const float* codebook = nullptr;
    const float* bias     = nullptr;
    const int*   indices  = nullptr;

    for (int i = 0; i < n_in; i++) {
        switch (in_sizes[i]) {
            case 33554432: x        = (const float*)d_in[i]; break;
            case 1048576:  codebook = (const float*)d_in[i]; break;
            case 4096:     bias     = (const float*)d_in[i]; break;
            case 16777216: indices  = (const int*)d_in[i];   break;
            default: break;
        }
    }
    float* out = (float*)d_out;   // [8192, 4096] fp32

    void* pX = nullptr; void* pW = nullptr;
    cudaGetSymbolAddress(&pX, g_X);
    cudaGetSymbolAddress(&pW, g_W);

    cudaFuncSetAttribute(gemm_kernel, cudaFuncAttributeMaxDynamicSharedMemorySize, SMEM_TOTAL);

    // 1) fused prologue: 16384 cvt blocks + 16384 decomp blocks, one launch
    prep_kernel<<<32768, 256>>>(x, indices, codebook, (__half*)pX, (__half*)pW);
    // 2) GEMM: grid (32 N-tiles fastest for L2 W-reuse within a wave, 64 M-tiles)
    gemm_kernel<<<dim3(N_TOT / TN, M_TOT / TM), 128, SMEM_TOTAL>>>(
        (const __half*)pX, (const __half*)pW, bias, out);
}

// round 15
// speedup vs baseline: 1.0718x; 1.0359x over previous
#include <cuda_runtime.h>
#include <cuda_fp16.h>
#include <cstdint>

// ---------------------------------------------------------------------------
// Problem dims
// ---------------------------------------------------------------------------
#define M_TOT 8192
#define N_TOT 4096
#define K_TOT 4096

// GEMM tiling: 128x128 CTA tile, 4 warps (2x2) of 64x64, 2 CTAs/SM (R12 config)
#define TM 128
#define TN 128
#define TK 64
#define STAGES 3
#define NKT (K_TOT / TK)                    // 64 k-iterations
#define A_STAGE_BYTES (TM * TK * 2)         // 16384
#define B_STAGE_BYTES (TN * TK * 2)         // 16384
#define STAGE_BYTES (A_STAGE_BYTES + B_STAGE_BYTES)   // 32768
#define SMEM_TOTAL (1024 + STAGES * STAGE_BYTES)      // 99328 (x2 CTAs = 194KB/SM)

// ---------------------------------------------------------------------------
// Scratch (allocation-guard-safe __device__ globals)
// ---------------------------------------------------------------------------
__device__ __half g_X[(size_t)M_TOT * K_TOT];   // 64 MB fp16 activations
__device__ __half g_W[(size_t)N_TOT * K_TOT];   // 32 MB fp16 decompressed weights

// ---------------------------------------------------------------------------
// PTX helpers (base-ISA only: cp.async sm_80, mbarrier, ldmatrix/mma)
// ---------------------------------------------------------------------------
__device__ __forceinline__ uint32_t smem_u32(const void* p) {
    uint32_t a;
    asm("{ .reg .u64 t; cvta.to.shared.u64 t, %1; cvt.u32.u64 %0, t; }" : "=r"(a) : "l"(p));
    return a;
}

__device__ __forceinline__ void cp_async16(uint32_t dst, const void* src) {
    asm volatile("cp.async.cg.shared.global [%0], [%1], 16;" :: "r"(dst), "l"(src) : "memory");
}

// streaming (evict-first) 8-byte store — keeps the 128MB output from
// displacing the L2-resident A/W working set
__device__ __forceinline__ void stg_cs_v2(float* p, float x, float y) {
    asm volatile("st.global.cs.v2.f32 [%0], {%1, %2};" :: "l"(p), "f"(x), "f"(y) : "memory");
}

#define MBARRIER_INIT(mbar, count) \
    asm volatile("mbarrier.init.shared.b64 [%0], %1;" :: "r"((uint32_t)(mbar)), "r"((uint32_t)(count)) : "memory")

#define MBARRIER_ARRIVE(mbar) \
    asm volatile("mbarrier.arrive.shared.b64 _, [%0];" :: "r"((uint32_t)(mbar)) : "memory")

// Arrive on mbar when ALL of this thread's prior cp.asyncs have completed.
#define CP_ASYNC_MBAR_ARRIVE(mbar) \
    asm volatile("cp.async.mbarrier.arrive.noinc.shared.b64 [%0];" :: "r"((uint32_t)(mbar)) : "memory")

#define MBARRIER_WAIT_PARITY(mbar, parity) do {                                     \
    uint32_t _m = (uint32_t)(mbar); uint32_t _p = (uint32_t)(parity); uint32_t _d;  \
    asm volatile("{\n\t.reg .pred p;\n\t"                                           \
        "mbarrier.try_wait.parity.acquire.cta.shared::cta.b64 p, [%1], %2;\n\t"     \
        "selp.b32 %0, 1, 0, p;\n\t}"                                                \
        : "=r"(_d) : "r"(_m), "r"(_p) : "memory");                                  \
    if (!_d) {                                                                      \
        asm volatile("{\n\t.reg .pred P1;\n\t"                                      \
            "WL_%=:\n\t"                                                            \
            "mbarrier.try_wait.parity.acquire.cta.shared::cta.b64 P1, [%0], %1, 0x989680;\n\t" \
            "@P1 bra.uni WD_%=;\n\t"                                                \
            "bra.uni WL_%=;\n\t"                                                    \
            "WD_%=:\n\t}"                                                           \
            :: "r"(_m), "r"(_p) : "memory");                                        \
    }                                                                               \
} while (0)

__device__ __forceinline__ void ldsm_x4(uint32_t& r0, uint32_t& r1, uint32_t& r2, uint32_t& r3,
                                        uint32_t addr) {
    asm volatile("ldmatrix.sync.aligned.m8n8.x4.shared.b16 {%0,%1,%2,%3}, [%4];"
                 : "=r"(r0), "=r"(r1), "=r"(r2), "=r"(r3) : "r"(addr));
}

__device__ __forceinline__ void mma16816(float* d, const uint32_t* a, const uint32_t* b) {
    asm volatile(
        "mma.sync.aligned.m16n8k16.row.col.f32.f16.f16.f32 "
        "{%0,%1,%2,%3}, {%4,%5,%6,%7}, {%8,%9}, {%0,%1,%2,%3};"
        : "+f"(d[0]), "+f"(d[1]), "+f"(d[2]), "+f"(d[3])
        : "r"(a[0]), "r"(a[1]), "r"(a[2]), "r"(a[3]), "r"(b[0]), "r"(b[1]));
}

// ---------------------------------------------------------------------------
// Kernel 1 (fused prologue): blocks [0, 16384) convert x fp32->fp16;
// blocks [16384, 32768) decompress W[o][i] = fp16(cb[o][idx[o][i]]).
// ---------------------------------------------------------------------------
__global__ void prep_kernel(const float* __restrict__ x,
                            const int* __restrict__ idx,
                            const float* __restrict__ cb,
                            __half* __restrict__ oX,
                            __half* __restrict__ oW) {
    int b = blockIdx.x;
    if (b < 16384) {
        size_t t = (size_t)b * blockDim.x + threadIdx.x;
        size_t base = t * 8;
        float4 a = *reinterpret_cast<const float4*>(x + base);
        float4 c = *reinterpret_cast<const float4*>(x + base + 4);
        __half2 h0 = __floats2half2_rn(a.x, a.y);
        __half2 h1 = __floats2half2_rn(a.z, a.w);
        __half2 h2 = __floats2half2_rn(c.x, c.y);
        __half2 h3 = __floats2half2_rn(c.z, c.w);
        uint4 u;
        u.x = *reinterpret_cast<uint32_t*>(&h0);
        u.y = *reinterpret_cast<uint32_t*>(&h1);
        u.z = *reinterpret_cast<uint32_t*>(&h2);
        u.w = *reinterpret_cast<uint32_t*>(&h3);
        *reinterpret_cast<uint4*>(oX + base) = u;
    } else {
        size_t t = (size_t)(b - 16384) * blockDim.x + threadIdx.x;
        size_t base = t * 4;
        int4 i4 = *reinterpret_cast<const int4*>(idx + base);
        const float* crow = cb + ((base >> 12) << 8);  // row = base/4096, *256 entries
        __half2 h0 = __floats2half2_rn(crow[i4.x], crow[i4.y]);
        __half2 h1 = __floats2half2_rn(crow[i4.z], crow[i4.w]);
        uint2 u;
        u.x = *reinterpret_cast<uint32_t*>(&h0);
        u.y = *reinterpret_cast<uint32_t*>(&h1);
        *reinterpret_cast<uint2*>(oW + base) = u;
    }
}

// ---------------------------------------------------------------------------
// Kernel 2: GEMM — R14 config (best: 651.3us, tensor 81.8%) with two micro
// edits: (1) MMAs issued nf-outer/mf-inner so the first HMMA of each k-step
// depends on the 5th ldsm instead of the 12th; (2) incremental slot/parity
// cursors replace per-iteration int div/mod on the ALU pipe.
// ---------------------------------------------------------------------------
__global__ void __launch_bounds__(128, 2) gemm_kernel(
    const __half* __restrict__ A,      // [M_TOT, K_TOT] row-major
    const __half* __restrict__ B,      // [N_TOT, K_TOT] row-major (= col-major B)
    const float* __restrict__ bias,
    float* __restrict__ out)
{
    extern __shared__ char smem[];
    const uint32_t sb = smem_u32(smem);
    const int tid = threadIdx.x, wid = tid >> 5, lane = tid & 31;
    const int warp_m = wid & 1;        // 2 warps along M
    const int warp_n = wid >> 1;       // 2 warps along N
    const int tile_n = blockIdx.x, tile_m = blockIdx.y;

    // mbarriers: full[0..2] at sb+0..23, empty[0..2] at sb+24..47; data at sb+1024
    const uint32_t BFULL  = sb;
    const uint32_t BEMPTY = sb + 8 * STAGES;
    const uint32_t DATA0  = sb + 1024;

    const __half* gA = A + (size_t)(tile_m * TM) * K_TOT;
    const __half* gB = B + (size_t)(tile_n * TN) * K_TOT;

    // cp.async (row, chunk): 8 chunks of 16B per 128B row, 16 rows/pass (128 thr)
    const int ld_row = tid >> 3;       // 0..15
    const int ld_ch  = tid & 7;
    const int ld_sw  = (ld_ch ^ (ld_row & 7)) << 4;

    if (tid == 0) {
        #pragma unroll
        for (int s = 0; s < STAGES; s++) {
            MBARRIER_INIT(BFULL + 8 * s, 128);   // one async-arrive per thread
            MBARRIER_INIT(BEMPTY + 8 * s, 4);    // one arrive per warp
        }
    }
    __syncthreads();

    // --- stage filler: 16 cp.asyncs per thread, then async-arrive on full[s] ---
    auto fill_stage = [&](int kt, int s) {
        uint32_t base = DATA0 + s * STAGE_BYTES;
        const __half* srcA = gA + kt * TK;
        #pragma unroll
        for (int i = 0; i < TM / 16; i++) {           // 8 iters: 128 rows
            int row = ld_row + i * 16;
            cp_async16(base + row * 128 + ld_sw, srcA + (size_t)row * K_TOT + ld_ch * 8);
        }
        uint32_t baseB = base + A_STAGE_BYTES;
        const __half* srcB = gB + kt * TK;
        #pragma unroll
        for (int i = 0; i < TN / 16; i++) {           // 8 iters: 128 rows
            int row = ld_row + i * 16;
            cp_async16(baseB + row * 128 + ld_sw, srcB + (size_t)row * K_TOT + ld_ch * 8);
        }
        CP_ASYNC_MBAR_ARRIVE(BFULL + 8 * s);
    };

    // --- ldmatrix per-lane geometry (64x64 warp tile) ---
    const int asub  = lane >> 3;
    const int a_row = warp_m * 64 + ((asub & 1) << 3) + (lane & 7);
    const int a_cof = asub >> 1;
    const int a_xor = a_row & 7;
    uint32_t aRowB[4];
    #pragma unroll
    for (int mf = 0; mf < 4; mf++) aRowB[mf] = (a_row + mf * 16) * 128;

    const int bsub  = lane >> 3;
    const int b_row = warp_n * 64 + ((bsub >> 1) << 3) + (lane & 7);
    const int b_cof = bsub & 1;
    const int b_xor = b_row & 7;
    uint32_t bRowB[4];
    #pragma unroll
    for (int p = 0; p < 4; p++) bRowB[p] = (b_row + p * 16) * 128;

    float acc[4][8][4];
    #pragma unroll
    for (int mf = 0; mf < 4; mf++)
        #pragma unroll
        for (int nf = 0; nf < 8; nf++)
            #pragma unroll
            for (int r = 0; r < 4; r++) acc[mf][nf][r] = 0.f;

    // --- bias preload (CTA-fixed columns; hides ~L2 latency off the epilogue) ---
    const int col0 = tile_n * TN + warp_n * 64 + ((lane & 3) << 1);
    float bv[8][2];
    #pragma unroll
    for (int nf = 0; nf < 8; nf++) {
        bv[nf][0] = __ldg(&bias[col0 + nf * 8]);
        bv[nf][1] = __ldg(&bias[col0 + nf * 8 + 1]);
    }

    // --- prologue: fill first STAGES-1 stages (slots never used before) ---
    #pragma unroll
    for (int s = 0; s < STAGES - 1; s++) fill_stage(s, s);

    // --- incremental cursors (no div/mod in the hot loop) ---
    int sC = 0, pC = 0;                    // consumer slot + full-parity
    int sP = STAGES - 1, wP = 0;           // producer slot + empty-wait parity
    bool needWait = false;                 // producer wait armed after 1st wrap

    // --- mainloop: mbarrier producer/consumer, no __syncthreads ---
    for (int kt = 0; kt < NKT; kt++) {
        MBARRIER_WAIT_PARITY(BFULL + 8 * sC, pC);
        uint32_t aBase = DATA0 + sC * STAGE_BYTES;
        uint32_t bBase = aBase + A_STAGE_BYTES;

        #pragma unroll
        for (int ks = 0; ks < TK / 16; ks++) {        // 4 k-steps of 16
            uint32_t af[4][4];
            #pragma unroll
            for (int mf = 0; mf < 4; mf++) {
                uint32_t addr = aBase + aRowB[mf] + ((((ks << 1) + a_cof) ^ a_xor) << 4);
                ldsm_x4(af[mf][0], af[mf][1], af[mf][2], af[mf][3], addr);
            }
            uint32_t bf[8][2];
            #pragma unroll
            for (int p = 0; p < 4; p++) {
                uint32_t r0, r1, r2, r3;
                uint32_t addr = bBase + bRowB[p] + ((((ks << 1) + b_cof) ^ b_xor) << 4);
                ldsm_x4(r0, r1, r2, r3, addr);
                bf[2 * p][0] = r0;     bf[2 * p][1] = r1;
                bf[2 * p + 1][0] = r2; bf[2 * p + 1][1] = r3;
            }
            // Last ldsm of this stage is done — release the slot early.
            if (ks == TK / 16 - 1 && lane == 0) MBARRIER_ARRIVE(BEMPTY + 8 * sC);
            // nf-outer: first HMMA depends on af[0..3] + bf[0] (5th ldsm),
            // and bf[nf] for later groups lands inside prior groups' issue.
            #pragma unroll
            for (int nf = 0; nf < 8; nf++)
                #pragma unroll
                for (int mf = 0; mf < 4; mf++)
                    mma16816(acc[mf][nf], af[mf], bf[nf]);
        }

        // produce: refill slot sP for k-tile kt+STAGES-1
        int ktL = kt + STAGES - 1;
        if (ktL < NKT) {
            if (needWait) MBARRIER_WAIT_PARITY(BEMPTY + 8 * sP, wP);
            fill_stage(ktL, sP);
            if (++sP == STAGES) {
                sP = 0;
                if (!needWait) needWait = true; else wP ^= 1;
            }
        }

        if (++sC == STAGES) { sC = 0; pC ^= 1; }
    }

    // --- epilogue: bias add + streaming fp32 stores (evict-first) ---
    const int row0 = tile_m * TM + warp_m * 64 + (lane >> 2);
    #pragma unroll
    for (int mf = 0; mf < 4; mf++) {
        #pragma unroll
        for (int h = 0; h < 2; h++) {
            size_t r = (size_t)(row0 + mf * 16 + h * 8);
            float* orow = out + r * N_TOT;
            #pragma unroll
            for (int nf = 0; nf < 8; nf++) {
                stg_cs_v2(orow + col0 + nf * 8,
                          acc[mf][nf][2 * h + 0] + bv[nf][0],
                          acc[mf][nf][2 * h + 1] + bv[nf][1]);
            }
        }
    }
}

// ---------------------------------------------------------------------------
// Host launch — inputs identified BY ELEMENT COUNT (robust to ordering):
//   x: 33554432 (f32), codebook: 1048576 (f32), bias: 4096 (f32),
//   indices: 16777216 (int32 — harness has no int64)
// ---------------------------------------------------------------------------
extern "C" void kernel_launch(void* const* d_in, const int* in_sizes, int n_in,
                              void* d_out, int out_size) {
    const float* x        = nullptr;
    const float* codebook = nullptr;
    const float* bias     = nullptr;
    const int*   indices  = nullptr;

    for (int i = 0; i < n_in; i++) {
        switch (in_sizes[i]) {
            case 33554432: x        = (const float*)d_in[i]; break;
            case 1048576:  codebook = (const float*)d_in[i]; break;
            case 4096:     bias     = (const float*)d_in[i]; break;
            case 16777216: indices  = (const int*)d_in[i];   break;
            default: break;
        }
    }
    float* out = (float*)d_out;   // [8192, 4096] fp32

    void* pX = nullptr; void* pW = nullptr;
    cudaGetSymbolAddress(&pX, g_X);
    cudaGetSymbolAddress(&pW, g_W);

    cudaFuncSetAttribute(gemm_kernel, cudaFuncAttributeMaxDynamicSharedMemorySize, SMEM_TOTAL);

    // 1) fused prologue: 16384 cvt blocks + 16384 decomp blocks, one launch
    prep_kernel<<<32768, 256>>>(x, indices, codebook, (__half*)pX, (__half*)pW);
    // 2) GEMM: grid (32 N-tiles fastest for L2 W-reuse within a wave, 64 M-tiles)
    gemm_kernel<<<dim3(N_TOT / TN, M_TOT / TM), 128, SMEM_TOTAL>>>(
        (const __half*)pX, (const __half*)pW, bias, out);
}